// round 12
// baseline (speedup 1.0000x reference)
#include <cuda_runtime.h>
#include <cuda_bf16.h>
#include <math_constants.h>
#include <cstdint>

#define BB 4
#define NN 1024
#define MM 65536
#define SCALE 1.5625f                 // 1/(64*0.01)
#define KSPLIT 4
#define TK 64
#define NCHUNK (MM/KSPLIT/TK)         // 256 chunks per CTA
#define MARGIN 9.0f                   // raw-dot units; 14 ln-units
#define CAP 2048

// ------------------------------------------------------------------ scratch
__device__ __nv_bfloat16 g_Qbf[BB*NN*64];          // [row][64]
__device__ float         g_Qf [BB*NN*64];          // [row][64]
__device__ __nv_bfloat16 g_Kbf[(size_t)BB*MM*64];  // [(b<<16)+m][64]
__device__ float         g_Kf [(size_t)BB*MM*64];  // [(b<<16)+m][64]
__device__ int           g_cnt[BB*NN];
__device__ unsigned short g_cand[(size_t)BB*NN*CAP];

// ------------------------------------------------------------------ helpers
__device__ __forceinline__ uint32_t smem_u32(const void* p) {
    uint32_t a;
    asm("{ .reg .u64 t; cvta.to.shared.u64 t, %1; cvt.u32.u64 %0, t; }" : "=r"(a) : "l"(p));
    return a;
}
__device__ __forceinline__ void cpa16(void* dst, const void* src) {
    uint32_t d = smem_u32(dst);
    asm volatile("cp.async.cg.shared.global [%0], [%1], 16;" :: "r"(d), "l"(src) : "memory");
}
#define CPA_COMMIT() asm volatile("cp.async.commit_group;" ::: "memory")
#define CPA_WAIT(n)  asm volatile("cp.async.wait_group %0;" :: "n"(n) : "memory")

__device__ __forceinline__ void mma_bf16(float4& d, const uint32_t* a, uint32_t b0, uint32_t b1) {
    asm volatile("mma.sync.aligned.m16n8k16.row.col.f32.bf16.bf16.f32 "
                 "{%0,%1,%2,%3},{%4,%5,%6,%7},{%8,%9},{%0,%1,%2,%3};"
                 : "+f"(d.x), "+f"(d.y), "+f"(d.z), "+f"(d.w)
                 : "r"(a[0]), "r"(a[1]), "r"(a[2]), "r"(a[3]), "r"(b0), "r"(b1));
}

// ------------------------------------------------------------------ preproc
__global__ void norm_src_kernel(const float* __restrict__ src_desc) {
    int gid = blockIdx.x * blockDim.x + threadIdx.x;   // 4096 rows
    int b = gid >> 10, n = gid & 1023;
    const float* p = src_desc + (size_t)b * 64 * NN + n;
    float xs[64]; float sum = 0.f;
#pragma unroll
    for (int c = 0; c < 64; c++) { xs[c] = p[c * NN]; sum += xs[c]; }
    float mean = sum * (1.f / 64.f), var = 0.f;
#pragma unroll
    for (int c = 0; c < 64; c++) { float d = xs[c] - mean; var += d * d; }
    float inv = rsqrtf(var * (1.f / 63.f));
#pragma unroll
    for (int c = 0; c < 64; c++) {
        float q = (xs[c] - mean) * inv;
        g_Qf[(size_t)gid * 64 + c]  = q;
        g_Qbf[(size_t)gid * 64 + c] = __float2bfloat16(q);
    }
}

__global__ void norm_tgt_kernel(const float* __restrict__ tgt_desc) {
    __shared__ uint32_t stg[8][32][33];
    int w = threadIdx.x >> 5, lane = threadIdx.x & 31;
    int gbase = blockIdx.x * 256 + w * 32;
    int gid = gbase + lane;                            // 0..262143
    int b = gid >> 16;
    int m = gid & 65535;
    const float* p = tgt_desc + (size_t)b * 64 * MM + m;
    float xs[64]; float sum = 0.f;
#pragma unroll
    for (int c = 0; c < 64; c++) { xs[c] = p[(size_t)c * MM]; sum += xs[c]; }
    float mean = sum * (1.f / 64.f), var = 0.f;
#pragma unroll
    for (int c = 0; c < 64; c++) { float d = xs[c] - mean; var += d * d; }
    float inv = rsqrtf(var * (1.f / 63.f));
    float kv[64];
#pragma unroll
    for (int c = 0; c < 64; c++) kv[c] = (xs[c] - mean) * inv;

    // bf16 transpose (rows of 64 bf16, coalesced 128B)
#pragma unroll
    for (int j = 0; j < 32; j++) {
        __nv_bfloat162 t; t.x = __float2bfloat16(kv[2 * j]); t.y = __float2bfloat16(kv[2 * j + 1]);
        stg[w][lane][j] = *(uint32_t*)&t;
    }
    __syncwarp();
    {
        uint32_t* dst = (uint32_t*)g_Kbf + (size_t)gbase * 32;
#pragma unroll
        for (int r = 0; r < 32; r++) dst[(size_t)r * 32 + lane] = stg[w][r][lane];
    }
    // fp32 transpose in two halves (rows of 64 f32)
#pragma unroll
    for (int h = 0; h < 2; h++) {
        __syncwarp();
#pragma unroll
        for (int j = 0; j < 32; j++) stg[w][lane][j] = __float_as_uint(kv[h * 32 + j]);
        __syncwarp();
        float* dst = g_Kf + (size_t)gbase * 64;
#pragma unroll
        for (int r = 0; r < 32; r++)
            dst[(size_t)r * 64 + h * 32 + lane] = __uint_as_float(stg[w][r][lane]);
    }
}

__global__ void zero_cnt_kernel() {
    int i = blockIdx.x * blockDim.x + threadIdx.x;
    if (i < BB * NN) g_cnt[i] = 0;
}

// ------------------------------------------------------------------ stage B: select candidates
#define SM_QB 0
#define SM_K0 (128*144)                 // two K buffers of 64 rows x 144B
#define KBUF  (64*144)
#define SM_TOTAL (SM_K0 + 2*KBUF)       // 36864 B

__global__ __launch_bounds__(256, 2) void select_kernel() {
    extern __shared__ char smem[];
    const int tid = threadIdx.x;
    const int warp = tid >> 5, lane = tid & 31;
    const int q4 = lane >> 2, t = lane & 3;
    const int ks = blockIdx.x, qt = blockIdx.y, b = blockIdx.z;
    const int kbase = ks * (MM / KSPLIT);

    // Q tile (bf16) to smem
    {
        const __nv_bfloat16* QB = g_Qbf + ((size_t)(b * 1024 + qt * 128)) * 64;
        for (int i = tid; i < 1024; i += 256) {
            int row = i >> 3, j = i & 7;
            *(float4*)(smem + SM_QB + row * 144 + j * 16) = *(const float4*)(QB + row * 64 + j * 8);
        }
    }
    // first K chunk
    {
        const __nv_bfloat16* KH = g_Kbf + (((size_t)b << 16) + kbase) * 64;
        int i = tid, row = i >> 3, j = i & 7;
        cpa16(smem + SM_K0 + row * 144 + j * 16, KH + row * 64 + j * 8);
        i = tid + 256; row = i >> 3; j = i & 7;
        cpa16(smem + SM_K0 + row * 144 + j * 16, KH + row * 64 + j * 8);
    }
    CPA_COMMIT();
    __syncthreads();

    // Q fragments
    uint32_t qh[4][4];
    {
        const int g = 16 * warp + q4;
        const char* QHs = smem + SM_QB;
#pragma unroll
        for (int kk = 0; kk < 4; kk++) {
            int c0 = kk * 16 + t * 2;
            qh[kk][0] = *(const uint32_t*)(QHs + g * 144 + c0 * 2);
            qh[kk][1] = *(const uint32_t*)(QHs + (g + 8) * 144 + c0 * 2);
            qh[kk][2] = *(const uint32_t*)(QHs + g * 144 + (c0 + 8) * 2);
            qh[kk][3] = *(const uint32_t*)(QHs + (g + 8) * 144 + (c0 + 8) * 2);
        }
    }

    const int r0 = 16 * warp + q4, r1 = r0 + 8;
    const int grow0 = b * 1024 + qt * 128 + r0;
    const int grow1 = grow0 + 8;
    float m_lo = -CUDART_INF_F, m_hi = -CUDART_INF_F;

    for (int i = 0; i < NCHUNK; i++) {
        char* cur = smem + SM_K0 + (i & 1) * KBUF;
        if (i + 1 < NCHUNK) {
            char* nxt = smem + SM_K0 + ((i + 1) & 1) * KBUF;
            const __nv_bfloat16* KH = g_Kbf + (((size_t)b << 16) + kbase + (i + 1) * TK) * 64;
            int u = tid, row = u >> 3, j = u & 7;
            cpa16(nxt + row * 144 + j * 16, KH + row * 64 + j * 8);
            u = tid + 256; row = u >> 3; j = u & 7;
            cpa16(nxt + row * 144 + j * 16, KH + row * 64 + j * 8);
            CPA_COMMIT();
            CPA_WAIT(1);
        } else {
            CPA_WAIT(0);
        }
        __syncthreads();

        // S = Q K^T, single bf16 pass
        float4 s[8];
        const int rb = q4 * 144 + t * 4;
#pragma unroll
        for (int nt = 0; nt < 8; nt++) {
            s[nt] = make_float4(0.f, 0.f, 0.f, 0.f);
            const char* kh = cur + nt * 8 * 144 + rb;
#pragma unroll
            for (int kk = 0; kk < 4; kk++) {
                uint32_t b0 = *(const uint32_t*)(kh + kk * 32);
                uint32_t b1 = *(const uint32_t*)(kh + kk * 32 + 16);
                mma_bf16(s[nt], qh[kk], b0, b1);
            }
        }

        // quad-reduced chunk max, update running max
        float mx_lo = -CUDART_INF_F, mx_hi = -CUDART_INF_F;
#pragma unroll
        for (int nt = 0; nt < 8; nt++) {
            mx_lo = fmaxf(mx_lo, fmaxf(s[nt].x, s[nt].y));
            mx_hi = fmaxf(mx_hi, fmaxf(s[nt].z, s[nt].w));
        }
        mx_lo = fmaxf(mx_lo, __shfl_xor_sync(0xffffffffu, mx_lo, 1));
        mx_lo = fmaxf(mx_lo, __shfl_xor_sync(0xffffffffu, mx_lo, 2));
        mx_hi = fmaxf(mx_hi, __shfl_xor_sync(0xffffffffu, mx_hi, 1));
        mx_hi = fmaxf(mx_hi, __shfl_xor_sync(0xffffffffu, mx_hi, 2));
        m_lo = fmaxf(m_lo, mx_lo);
        m_hi = fmaxf(m_hi, mx_hi);
        const float thr0 = m_lo - MARGIN, thr1 = m_hi - MARGIN;

        // emit candidates
        const int kb = kbase + i * TK + 2 * t;
#pragma unroll
        for (int nt = 0; nt < 8; nt++) {
            int key = kb + nt * 8;
            if (s[nt].x > thr0) {
                int pos = atomicAdd(&g_cnt[grow0], 1);
                if (pos < CAP) g_cand[(size_t)grow0 * CAP + pos] = (unsigned short)key;
            }
            if (s[nt].y > thr0) {
                int pos = atomicAdd(&g_cnt[grow0], 1);
                if (pos < CAP) g_cand[(size_t)grow0 * CAP + pos] = (unsigned short)(key + 1);
            }
            if (s[nt].z > thr1) {
                int pos = atomicAdd(&g_cnt[grow1], 1);
                if (pos < CAP) g_cand[(size_t)grow1 * CAP + pos] = (unsigned short)key;
            }
            if (s[nt].w > thr1) {
                int pos = atomicAdd(&g_cnt[grow1], 1);
                if (pos < CAP) g_cand[(size_t)grow1 * CAP + pos] = (unsigned short)(key + 1);
            }
        }
        __syncthreads();
    }
}

// ------------------------------------------------------------------ stage C: exact recompute + epilogue
__global__ __launch_bounds__(128) void finalize_kernel(const float* __restrict__ tgt_desc,
                                                       const float* __restrict__ tgt_coords,
                                                       const float* __restrict__ tgt_w,
                                                       float* __restrict__ out) {
    __shared__ float qsh[64];
    __shared__ unsigned short candi[CAP];
    __shared__ float sv[CAP];
    __shared__ float red[8];
    __shared__ float vals[68];
    __shared__ float stats[2];

    const int row = blockIdx.x;           // 0..4095
    const int tid = threadIdx.x;
    const int b = row >> 10, n = row & 1023;
    const int nc = min(g_cnt[row], CAP);

    if (tid < 64) qsh[tid] = g_Qf[(size_t)row * 64 + tid];
    for (int c = tid; c < nc; c += 128) candi[c] = g_cand[(size_t)row * CAP + c];
    __syncthreads();

    // exact fp32 dots
    const float4* q4p = (const float4*)qsh;
    for (int c = tid; c < nc; c += 128) {
        const float4* kr = (const float4*)(g_Kf + ((((size_t)b << 16) + candi[c])) * 64);
        float acc = 0.f;
#pragma unroll
        for (int j = 0; j < 16; j++) {
            float4 kv = kr[j], qv = q4p[j];
            acc += kv.x * qv.x + kv.y * qv.y + kv.z * qv.z + kv.w * qv.w;
        }
        sv[c] = acc;
    }
    __syncthreads();

    // block max
    float mx = -CUDART_INF_F;
    for (int c = tid; c < nc; c += 128) mx = fmaxf(mx, sv[c]);
#pragma unroll
    for (int o = 16; o; o >>= 1) mx = fmaxf(mx, __shfl_xor_sync(0xffffffffu, mx, o));
    if ((tid & 31) == 0) red[tid >> 5] = mx;
    __syncthreads();
    mx = fmaxf(fmaxf(red[0], red[1]), fmaxf(red[2], red[3]));

    // p and L
    float Lp = 0.f;
    for (int c = tid; c < nc; c += 128) {
        float p = __expf(SCALE * (sv[c] - mx));
        sv[c] = p;
        Lp += p;
    }
#pragma unroll
    for (int o = 16; o; o >>= 1) Lp += __shfl_xor_sync(0xffffffffu, Lp, o);
    if ((tid & 31) == 0) red[4 + (tid >> 5)] = Lp;
    __syncthreads();
    float L = red[4] + red[5] + red[6] + red[7];
    float invL = 1.f / L;

    // weighted channel sums
    if (tid < 68) {
        const float* base;
        if (tid < 64)      base = tgt_desc + (((size_t)(b * 64 + tid)) << 16);
        else if (tid < 67) base = tgt_coords + (((size_t)(b * 3 + tid - 64)) << 16);
        else               base = tgt_w + (((size_t)b) << 16);
        float acc = 0.f;
#pragma unroll 4
        for (int c = 0; c < nc; c++) acc += sv[c] * base[candi[c]];
        vals[tid] = acc * invL;
    }
    __syncthreads();

    if (tid == 0) {
        float sum = 0.f;
#pragma unroll
        for (int c = 0; c < 64; c++) sum += vals[c];
        float mean = sum * (1.f / 64.f), var = 0.f;
#pragma unroll
        for (int c = 0; c < 64; c++) { float d = vals[c] - mean; var += d * d; }
        stats[0] = mean;
        stats[1] = rsqrtf(var * (1.f / 63.f));
    }
    __syncthreads();

    if (tid < 64)
        out[16384 + (b * 64 + tid) * 1024 + n] = (vals[tid] - stats[0]) * stats[1];

    if (tid == 64) {
        float x = vals[64], y = vals[65], z = vals[66], wgt = vals[67];
        out[(b * 3 + 0) * 1024 + n] = x;
        out[(b * 3 + 1) * 1024 + n] = y;
        out[(b * 3 + 2) * 1024 + n] = z;
        out[12288 + b * 1024 + n] = wgt;
        float rr = sqrtf(x * x + y * y + z * z);
        float az = atan2f(y, x);
        float el = asinf(z / (rr + 1e-12f));
        float u = 0.5f * (1.0f - az * (1.0f / CUDART_PI_F)) * 1024.0f;
        float v = (1.0f - (el + 0.4363323129985824f) * (1.0f / 0.4886921905584123f)) * 64.0f;
        u = fminf(fmaxf(u, 0.f), 1023.f);
        v = fminf(fmaxf(v, 0.f), 63.f);
        out[278528 + row * 2 + 0] = u;
        out[278528 + row * 2 + 1] = v;
        out[286720 + b * 1024 + n] = 1.0f;
    }
}

// ------------------------------------------------------------------
extern "C" void kernel_launch(void* const* d_in, const int* in_sizes, int n_in,
                              void* d_out, int out_size) {
    const float* tgt_coords = (const float*)d_in[1];
    const float* tgt_w      = (const float*)d_in[2];
    const float* src_desc   = (const float*)d_in[3];
    const float* tgt_desc   = (const float*)d_in[4];
    float* out = (float*)d_out;

    cudaFuncSetAttribute(select_kernel, cudaFuncAttributeMaxDynamicSharedMemorySize, SM_TOTAL);

    norm_src_kernel<<<16, 256>>>(src_desc);
    norm_tgt_kernel<<<1024, 256>>>(tgt_desc);
    zero_cnt_kernel<<<16, 256>>>();
    select_kernel<<<dim3(KSPLIT, 8, BB), 256, SM_TOTAL>>>();
    finalize_kernel<<<BB * NN, 128>>>(tgt_desc, tgt_coords, tgt_w, out);
}

// round 13
// speedup vs baseline: 2.8201x; 2.8201x over previous
#include <cuda_runtime.h>
#include <cuda_bf16.h>
#include <math_constants.h>
#include <cstdint>

#define BB 4
#define NN 1024
#define MM 65536
#define SCALE 1.5625f                 // 1/(64*0.01)
#define KSPLIT 8
#define TK 64
#define NCHUNK (MM/KSPLIT/TK)         // 128 chunks per CTA
#define MARGIN 7.5f                   // select margin (raw units; ln 11.7)
#define PRUNE  7.0f                   // finalize prune margin (raw; ln 10.9)
#define CAP 2048
#define NSCAP 512

// ------------------------------------------------------------------ scratch
__device__ __nv_bfloat16 g_Qbf[BB*NN*64];          // [row][64]
__device__ float         g_Qf [BB*NN*64];          // [row][64]
__device__ __nv_bfloat16 g_Kbf[(size_t)BB*MM*64];  // [(b<<16)+m][64]
__device__ float         g_Kf [(size_t)BB*MM*64];  // [(b<<16)+m][64]
__device__ int           g_cnt[BB*NN];
__device__ uint32_t      g_cand[(size_t)BB*NN*CAP]; // (float-hi16 | key)

// ------------------------------------------------------------------ helpers
__device__ __forceinline__ uint32_t smem_u32(const void* p) {
    uint32_t a;
    asm("{ .reg .u64 t; cvta.to.shared.u64 t, %1; cvt.u32.u64 %0, t; }" : "=r"(a) : "l"(p));
    return a;
}
__device__ __forceinline__ void cpa16(void* dst, const void* src) {
    uint32_t d = smem_u32(dst);
    asm volatile("cp.async.cg.shared.global [%0], [%1], 16;" :: "r"(d), "l"(src) : "memory");
}
#define CPA_COMMIT() asm volatile("cp.async.commit_group;" ::: "memory")
#define CPA_WAIT(n)  asm volatile("cp.async.wait_group %0;" :: "n"(n) : "memory")

__device__ __forceinline__ void mma_bf16(float4& d, const uint32_t* a, uint32_t b0, uint32_t b1) {
    asm volatile("mma.sync.aligned.m16n8k16.row.col.f32.bf16.bf16.f32 "
                 "{%0,%1,%2,%3},{%4,%5,%6,%7},{%8,%9},{%0,%1,%2,%3};"
                 : "+f"(d.x), "+f"(d.y), "+f"(d.z), "+f"(d.w)
                 : "r"(a[0]), "r"(a[1]), "r"(a[2]), "r"(a[3]), "r"(b0), "r"(b1));
}
__device__ __forceinline__ uint32_t packsv(float v, int key) {
    return (__float_as_uint(v) & 0xFFFF0000u) | (uint32_t)key;
}
__device__ __forceinline__ float unpackv(uint32_t p) {
    return __uint_as_float(p & 0xFFFF0000u);
}

// ------------------------------------------------------------------ preproc
__global__ void norm_src_kernel(const float* __restrict__ src_desc) {
    int gid = blockIdx.x * blockDim.x + threadIdx.x;   // 4096 rows
    int b = gid >> 10, n = gid & 1023;
    const float* p = src_desc + (size_t)b * 64 * NN + n;
    float xs[64]; float sum = 0.f;
#pragma unroll
    for (int c = 0; c < 64; c++) { xs[c] = p[c * NN]; sum += xs[c]; }
    float mean = sum * (1.f / 64.f), var = 0.f;
#pragma unroll
    for (int c = 0; c < 64; c++) { float d = xs[c] - mean; var += d * d; }
    float inv = rsqrtf(var * (1.f / 63.f));
#pragma unroll
    for (int c = 0; c < 64; c++) {
        float q = (xs[c] - mean) * inv;
        g_Qf[(size_t)gid * 64 + c]  = q;
        g_Qbf[(size_t)gid * 64 + c] = __float2bfloat16(q);
    }
}

__global__ void norm_tgt_kernel(const float* __restrict__ tgt_desc) {
    __shared__ uint32_t stg[8][32][33];
    int w = threadIdx.x >> 5, lane = threadIdx.x & 31;
    int gbase = blockIdx.x * 256 + w * 32;
    int gid = gbase + lane;                            // 0..262143
    int b = gid >> 16;
    int m = gid & 65535;
    const float* p = tgt_desc + (size_t)b * 64 * MM + m;
    float xs[64]; float sum = 0.f;
#pragma unroll
    for (int c = 0; c < 64; c++) { xs[c] = p[(size_t)c * MM]; sum += xs[c]; }
    float mean = sum * (1.f / 64.f), var = 0.f;
#pragma unroll
    for (int c = 0; c < 64; c++) { float d = xs[c] - mean; var += d * d; }
    float inv = rsqrtf(var * (1.f / 63.f));
    float kv[64];
#pragma unroll
    for (int c = 0; c < 64; c++) kv[c] = (xs[c] - mean) * inv;

    // bf16 transpose (rows of 64 bf16, coalesced 128B)
#pragma unroll
    for (int j = 0; j < 32; j++) {
        __nv_bfloat162 t; t.x = __float2bfloat16(kv[2 * j]); t.y = __float2bfloat16(kv[2 * j + 1]);
        stg[w][lane][j] = *(uint32_t*)&t;
    }
    __syncwarp();
    {
        uint32_t* dst = (uint32_t*)g_Kbf + (size_t)gbase * 32;
#pragma unroll
        for (int r = 0; r < 32; r++) dst[(size_t)r * 32 + lane] = stg[w][r][lane];
    }
    // fp32 transpose in two halves (rows of 64 f32)
#pragma unroll
    for (int h = 0; h < 2; h++) {
        __syncwarp();
#pragma unroll
        for (int j = 0; j < 32; j++) stg[w][lane][j] = __float_as_uint(kv[h * 32 + j]);
        __syncwarp();
        float* dst = g_Kf + (size_t)gbase * 64;
#pragma unroll
        for (int r = 0; r < 32; r++)
            dst[(size_t)r * 64 + h * 32 + lane] = __uint_as_float(stg[w][r][lane]);
    }
}

__global__ void zero_cnt_kernel() {
    int i = blockIdx.x * blockDim.x + threadIdx.x;
    if (i < BB * NN) g_cnt[i] = 0;
}

// ------------------------------------------------------------------ stage B: select candidates
#define SM_QB 0
#define SM_K0 (128*144)                 // two K buffers of 64 rows x 144B
#define KBUF  (64*144)
#define SM_TOTAL (SM_K0 + 2*KBUF)       // 36864 B

__global__ __launch_bounds__(256, 2) void select_kernel() {
    extern __shared__ char smem[];
    const int tid = threadIdx.x;
    const int warp = tid >> 5, lane = tid & 31;
    const int q4 = lane >> 2, t = lane & 3;
    const int ks = blockIdx.x, qt = blockIdx.y, b = blockIdx.z;
    const int kbase = ks * (MM / KSPLIT);

    // Q tile (bf16) to smem
    {
        const __nv_bfloat16* QB = g_Qbf + ((size_t)(b * 1024 + qt * 128)) * 64;
        for (int i = tid; i < 1024; i += 256) {
            int row = i >> 3, j = i & 7;
            *(float4*)(smem + SM_QB + row * 144 + j * 16) = *(const float4*)(QB + row * 64 + j * 8);
        }
    }
    // first K chunk
    {
        const __nv_bfloat16* KH = g_Kbf + (((size_t)b << 16) + kbase) * 64;
        int i = tid, row = i >> 3, j = i & 7;
        cpa16(smem + SM_K0 + row * 144 + j * 16, KH + row * 64 + j * 8);
        i = tid + 256; row = i >> 3; j = i & 7;
        cpa16(smem + SM_K0 + row * 144 + j * 16, KH + row * 64 + j * 8);
    }
    CPA_COMMIT();
    __syncthreads();

    // Q fragments
    uint32_t qh[4][4];
    {
        const int g = 16 * warp + q4;
        const char* QHs = smem + SM_QB;
#pragma unroll
        for (int kk = 0; kk < 4; kk++) {
            int c0 = kk * 16 + t * 2;
            qh[kk][0] = *(const uint32_t*)(QHs + g * 144 + c0 * 2);
            qh[kk][1] = *(const uint32_t*)(QHs + (g + 8) * 144 + c0 * 2);
            qh[kk][2] = *(const uint32_t*)(QHs + g * 144 + (c0 + 8) * 2);
            qh[kk][3] = *(const uint32_t*)(QHs + (g + 8) * 144 + (c0 + 8) * 2);
        }
    }

    const int r0 = 16 * warp + q4, r1 = r0 + 8;
    const int grow0 = b * 1024 + qt * 128 + r0;
    const int grow1 = grow0 + 8;
    float m_lo = -CUDART_INF_F, m_hi = -CUDART_INF_F;

    for (int i = 0; i < NCHUNK; i++) {
        char* cur = smem + SM_K0 + (i & 1) * KBUF;
        if (i + 1 < NCHUNK) {
            char* nxt = smem + SM_K0 + ((i + 1) & 1) * KBUF;
            const __nv_bfloat16* KH = g_Kbf + (((size_t)b << 16) + kbase + (i + 1) * TK) * 64;
            int u = tid, row = u >> 3, j = u & 7;
            cpa16(nxt + row * 144 + j * 16, KH + row * 64 + j * 8);
            u = tid + 256; row = u >> 3; j = u & 7;
            cpa16(nxt + row * 144 + j * 16, KH + row * 64 + j * 8);
            CPA_COMMIT();
            CPA_WAIT(1);
        } else {
            CPA_WAIT(0);
        }
        __syncthreads();

        // S = Q K^T, single bf16 pass
        float4 s[8];
        const int rb = q4 * 144 + t * 4;
#pragma unroll
        for (int nt = 0; nt < 8; nt++) {
            s[nt] = make_float4(0.f, 0.f, 0.f, 0.f);
            const char* kh = cur + nt * 8 * 144 + rb;
#pragma unroll
            for (int kk = 0; kk < 4; kk++) {
                uint32_t b0 = *(const uint32_t*)(kh + kk * 32);
                uint32_t b1 = *(const uint32_t*)(kh + kk * 32 + 16);
                mma_bf16(s[nt], qh[kk], b0, b1);
            }
        }

        // quad-reduced chunk max, update running max
        float mx_lo = -CUDART_INF_F, mx_hi = -CUDART_INF_F;
#pragma unroll
        for (int nt = 0; nt < 8; nt++) {
            mx_lo = fmaxf(mx_lo, fmaxf(s[nt].x, s[nt].y));
            mx_hi = fmaxf(mx_hi, fmaxf(s[nt].z, s[nt].w));
        }
        mx_lo = fmaxf(mx_lo, __shfl_xor_sync(0xffffffffu, mx_lo, 1));
        mx_lo = fmaxf(mx_lo, __shfl_xor_sync(0xffffffffu, mx_lo, 2));
        mx_hi = fmaxf(mx_hi, __shfl_xor_sync(0xffffffffu, mx_hi, 1));
        mx_hi = fmaxf(mx_hi, __shfl_xor_sync(0xffffffffu, mx_hi, 2));
        m_lo = fmaxf(m_lo, mx_lo);
        m_hi = fmaxf(m_hi, mx_hi);
        const float thr0 = m_lo - MARGIN, thr1 = m_hi - MARGIN;

        // emit candidates (warp-gated: most chunks have nothing near the max)
        bool near = (mx_lo > thr0) || (mx_hi > thr1);
        if (__any_sync(0xffffffffu, near)) {
            const int kb = kbase + i * TK + 2 * t;
#pragma unroll
            for (int nt = 0; nt < 8; nt++) {
                int key = kb + nt * 8;
                if (s[nt].x > thr0) {
                    int pos = atomicAdd(&g_cnt[grow0], 1);
                    if (pos < CAP) g_cand[(size_t)grow0 * CAP + pos] = packsv(s[nt].x, key);
                }
                if (s[nt].y > thr0) {
                    int pos = atomicAdd(&g_cnt[grow0], 1);
                    if (pos < CAP) g_cand[(size_t)grow0 * CAP + pos] = packsv(s[nt].y, key + 1);
                }
                if (s[nt].z > thr1) {
                    int pos = atomicAdd(&g_cnt[grow1], 1);
                    if (pos < CAP) g_cand[(size_t)grow1 * CAP + pos] = packsv(s[nt].z, key);
                }
                if (s[nt].w > thr1) {
                    int pos = atomicAdd(&g_cnt[grow1], 1);
                    if (pos < CAP) g_cand[(size_t)grow1 * CAP + pos] = packsv(s[nt].w, key + 1);
                }
            }
        }
        __syncthreads();
    }
}

// ------------------------------------------------------------------ stage C: prune + exact recompute + epilogue
__global__ __launch_bounds__(128) void finalize_kernel(const float* __restrict__ tgt_desc,
                                                       const float* __restrict__ tgt_coords,
                                                       const float* __restrict__ tgt_w,
                                                       float* __restrict__ out) {
    __shared__ float qsh[64];
    __shared__ uint32_t pairs[CAP];
    __shared__ unsigned short skey[NSCAP];
    __shared__ float sval[NSCAP];
    __shared__ float redA[4], redB[4], redC[4];
    __shared__ int s_ns;
    __shared__ float vals[68];
    __shared__ float stats[2];

    const int row = blockIdx.x;           // 0..4095
    const int tid = threadIdx.x;
    const int lane = tid & 31, wp = tid >> 5;
    const int b = row >> 10, n = row & 1023;
    const int nc = min(g_cnt[row], CAP);

    if (tid < 64) qsh[tid] = g_Qf[(size_t)row * 64 + tid];
    if (tid == 0) s_ns = 0;

    // 1. load pairs (coalesced), bf16-score max
    float mx = -CUDART_INF_F;
    for (int c = tid; c < nc; c += 128) {
        uint32_t p = g_cand[(size_t)row * CAP + c];
        pairs[c] = p;
        mx = fmaxf(mx, unpackv(p));
    }
#pragma unroll
    for (int o = 16; o; o >>= 1) mx = fmaxf(mx, __shfl_xor_sync(0xffffffffu, mx, o));
    if (lane == 0) redA[wp] = mx;
    __syncthreads();
    mx = fmaxf(fmaxf(redA[0], redA[1]), fmaxf(redA[2], redA[3]));

    // 2. prune + compact survivors
    const float thr = mx - PRUNE;
    for (int c = tid; c < nc; c += 128) {
        uint32_t p = pairs[c];
        if (unpackv(p) > thr) {
            int pos = atomicAdd(&s_ns, 1);
            if (pos < NSCAP) skey[pos] = (unsigned short)(p & 0xFFFFu);
        }
    }
    __syncthreads();
    const int ns = min(s_ns, NSCAP);

    // 3. exact fp32 dots over survivors
    const float4* q4p = (const float4*)qsh;
    for (int c = tid; c < ns; c += 128) {
        const float4* kr = (const float4*)(g_Kf + ((((size_t)b << 16) + skey[c])) * 64);
        float acc = 0.f;
#pragma unroll
        for (int j = 0; j < 16; j++) {
            float4 kv = kr[j], qv = q4p[j];
            acc += kv.x * qv.x + kv.y * qv.y + kv.z * qv.z + kv.w * qv.w;
        }
        sval[c] = acc;
    }
    __syncthreads();

    // 4. exact max
    float m2 = -CUDART_INF_F;
    for (int c = tid; c < ns; c += 128) m2 = fmaxf(m2, sval[c]);
#pragma unroll
    for (int o = 16; o; o >>= 1) m2 = fmaxf(m2, __shfl_xor_sync(0xffffffffu, m2, o));
    if (lane == 0) redB[wp] = m2;
    __syncthreads();
    m2 = fmaxf(fmaxf(redB[0], redB[1]), fmaxf(redB[2], redB[3]));

    // 5. p and L
    float Lp = 0.f;
    for (int c = tid; c < ns; c += 128) {
        float p = __expf(SCALE * (sval[c] - m2));
        sval[c] = p;
        Lp += p;
    }
#pragma unroll
    for (int o = 16; o; o >>= 1) Lp += __shfl_xor_sync(0xffffffffu, Lp, o);
    if (lane == 0) redC[wp] = Lp;
    __syncthreads();
    const float invL = 1.f / (redC[0] + redC[1] + redC[2] + redC[3]);

    // 6. weighted channel sums over survivors only
    if (tid < 68) {
        const float* base;
        if (tid < 64)      base = tgt_desc + (((size_t)(b * 64 + tid)) << 16);
        else if (tid < 67) base = tgt_coords + (((size_t)(b * 3 + tid - 64)) << 16);
        else               base = tgt_w + (((size_t)b) << 16);
        float acc = 0.f;
        for (int c = 0; c < ns; c++) acc += sval[c] * base[skey[c]];
        vals[tid] = acc * invL;
    }
    __syncthreads();

    if (tid == 0) {
        float sum = 0.f;
#pragma unroll
        for (int c = 0; c < 64; c++) sum += vals[c];
        float mean = sum * (1.f / 64.f), var = 0.f;
#pragma unroll
        for (int c = 0; c < 64; c++) { float d = vals[c] - mean; var += d * d; }
        stats[0] = mean;
        stats[1] = rsqrtf(var * (1.f / 63.f));
    }
    __syncthreads();

    if (tid < 64)
        out[16384 + (b * 64 + tid) * 1024 + n] = (vals[tid] - stats[0]) * stats[1];

    if (tid == 64) {
        float x = vals[64], y = vals[65], z = vals[66], wgt = vals[67];
        out[(b * 3 + 0) * 1024 + n] = x;
        out[(b * 3 + 1) * 1024 + n] = y;
        out[(b * 3 + 2) * 1024 + n] = z;
        out[12288 + b * 1024 + n] = wgt;
        float rr = sqrtf(x * x + y * y + z * z);
        float az = atan2f(y, x);
        float el = asinf(z / (rr + 1e-12f));
        float u = 0.5f * (1.0f - az * (1.0f / CUDART_PI_F)) * 1024.0f;
        float v = (1.0f - (el + 0.4363323129985824f) * (1.0f / 0.4886921905584123f)) * 64.0f;
        u = fminf(fmaxf(u, 0.f), 1023.f);
        v = fminf(fmaxf(v, 0.f), 63.f);
        out[278528 + row * 2 + 0] = u;
        out[278528 + row * 2 + 1] = v;
        out[286720 + b * 1024 + n] = 1.0f;
    }
}

// ------------------------------------------------------------------
extern "C" void kernel_launch(void* const* d_in, const int* in_sizes, int n_in,
                              void* d_out, int out_size) {
    const float* tgt_coords = (const float*)d_in[1];
    const float* tgt_w      = (const float*)d_in[2];
    const float* src_desc   = (const float*)d_in[3];
    const float* tgt_desc   = (const float*)d_in[4];
    float* out = (float*)d_out;

    cudaFuncSetAttribute(select_kernel, cudaFuncAttributeMaxDynamicSharedMemorySize, SM_TOTAL);

    norm_src_kernel<<<16, 256>>>(src_desc);
    norm_tgt_kernel<<<1024, 256>>>(tgt_desc);
    zero_cnt_kernel<<<16, 256>>>();
    select_kernel<<<dim3(KSPLIT, 8, BB), 256, SM_TOTAL>>>();
    finalize_kernel<<<BB * NN, 128>>>(tgt_desc, tgt_coords, tgt_w, out);
}

// round 14
// speedup vs baseline: 4.0734x; 1.4444x over previous
#include <cuda_runtime.h>
#include <cuda_bf16.h>
#include <math_constants.h>
#include <cstdint>

#define BB 4
#define NN 1024
#define MM 65536
#define SCALE 1.5625f                 // 1/(64*0.01)
#define KSPLIT 8
#define TK 64
#define NCHUNK (MM/KSPLIT/TK)         // 128 chunks per CTA
#define MARGIN 7.5f                   // select margin (raw units)
#define PRUNE  7.0f                   // finalize prune margin (raw, exact dots)
#define CAP 2048
#define NSCAP 512

// ------------------------------------------------------------------ scratch
__device__ __nv_bfloat16 g_Qbf[BB*NN*64];          // [row][64]
__device__ float         g_Qf [BB*NN*64];          // [row][64]
__device__ __nv_bfloat16 g_Kbf[(size_t)BB*MM*64];  // [(b<<16)+m][64]
__device__ float         g_Kf [(size_t)BB*MM*64];  // [(b<<16)+m][64]
__device__ int           g_cnt[BB*NN];
__device__ unsigned short g_cand[(size_t)BB*NN*CAP];

// ------------------------------------------------------------------ helpers
__device__ __forceinline__ uint32_t smem_u32(const void* p) {
    uint32_t a;
    asm("{ .reg .u64 t; cvta.to.shared.u64 t, %1; cvt.u32.u64 %0, t; }" : "=r"(a) : "l"(p));
    return a;
}
__device__ __forceinline__ void cpa16(void* dst, const void* src) {
    uint32_t d = smem_u32(dst);
    asm volatile("cp.async.cg.shared.global [%0], [%1], 16;" :: "r"(d), "l"(src) : "memory");
}
#define CPA_COMMIT() asm volatile("cp.async.commit_group;" ::: "memory")
#define CPA_WAIT(n)  asm volatile("cp.async.wait_group %0;" :: "n"(n) : "memory")

__device__ __forceinline__ void mma_bf16(float4& d, const uint32_t* a, uint32_t b0, uint32_t b1) {
    asm volatile("mma.sync.aligned.m16n8k16.row.col.f32.bf16.bf16.f32 "
                 "{%0,%1,%2,%3},{%4,%5,%6,%7},{%8,%9},{%0,%1,%2,%3};"
                 : "+f"(d.x), "+f"(d.y), "+f"(d.z), "+f"(d.w)
                 : "r"(a[0]), "r"(a[1]), "r"(a[2]), "r"(a[3]), "r"(b0), "r"(b1));
}

// ------------------------------------------------------------------ preproc
__global__ void norm_src_kernel(const float* __restrict__ src_desc) {
    int gid = blockIdx.x * blockDim.x + threadIdx.x;   // 4096 rows
    int b = gid >> 10, n = gid & 1023;
    const float* p = src_desc + (size_t)b * 64 * NN + n;
    float xs[64]; float sum = 0.f;
#pragma unroll
    for (int c = 0; c < 64; c++) { xs[c] = p[c * NN]; sum += xs[c]; }
    float mean = sum * (1.f / 64.f), var = 0.f;
#pragma unroll
    for (int c = 0; c < 64; c++) { float d = xs[c] - mean; var += d * d; }
    float inv = rsqrtf(var * (1.f / 63.f));
#pragma unroll
    for (int c = 0; c < 64; c++) {
        float q = (xs[c] - mean) * inv;
        g_Qf[(size_t)gid * 64 + c]  = q;
        g_Qbf[(size_t)gid * 64 + c] = __float2bfloat16(q);
    }
}

__global__ void norm_tgt_kernel(const float* __restrict__ tgt_desc) {
    __shared__ uint32_t stg[8][32][33];
    int w = threadIdx.x >> 5, lane = threadIdx.x & 31;
    int gbase = blockIdx.x * 256 + w * 32;
    int gid = gbase + lane;                            // 0..262143
    int b = gid >> 16;
    int m = gid & 65535;
    const float* p = tgt_desc + (size_t)b * 64 * MM + m;
    float xs[64]; float sum = 0.f;
#pragma unroll
    for (int c = 0; c < 64; c++) { xs[c] = p[(size_t)c * MM]; sum += xs[c]; }
    float mean = sum * (1.f / 64.f), var = 0.f;
#pragma unroll
    for (int c = 0; c < 64; c++) { float d = xs[c] - mean; var += d * d; }
    float inv = rsqrtf(var * (1.f / 63.f));
    float kv[64];
#pragma unroll
    for (int c = 0; c < 64; c++) kv[c] = (xs[c] - mean) * inv;

    // bf16 transpose (rows of 64 bf16, coalesced 128B)
#pragma unroll
    for (int j = 0; j < 32; j++) {
        __nv_bfloat162 t; t.x = __float2bfloat16(kv[2 * j]); t.y = __float2bfloat16(kv[2 * j + 1]);
        stg[w][lane][j] = *(uint32_t*)&t;
    }
    __syncwarp();
    {
        uint32_t* dst = (uint32_t*)g_Kbf + (size_t)gbase * 32;
#pragma unroll
        for (int r = 0; r < 32; r++) dst[(size_t)r * 32 + lane] = stg[w][r][lane];
    }
    // fp32 transpose in two halves (rows of 64 f32)
#pragma unroll
    for (int h = 0; h < 2; h++) {
        __syncwarp();
#pragma unroll
        for (int j = 0; j < 32; j++) stg[w][lane][j] = __float_as_uint(kv[h * 32 + j]);
        __syncwarp();
        float* dst = g_Kf + (size_t)gbase * 64;
#pragma unroll
        for (int r = 0; r < 32; r++)
            dst[(size_t)r * 64 + h * 32 + lane] = __uint_as_float(stg[w][r][lane]);
    }
}

__global__ void zero_cnt_kernel() {
    int i = blockIdx.x * blockDim.x + threadIdx.x;
    if (i < BB * NN) g_cnt[i] = 0;
}

// ------------------------------------------------------------------ stage B: select candidates
#define SM_QB 0
#define SM_K0 (128*144)                 // two K buffers of 64 rows x 144B
#define KBUF  (64*144)
#define SM_TOTAL (SM_K0 + 2*KBUF)       // 36864 B

__global__ __launch_bounds__(256, 2) void select_kernel() {
    extern __shared__ char smem[];
    const int tid = threadIdx.x;
    const int warp = tid >> 5, lane = tid & 31;
    const int q4 = lane >> 2, t = lane & 3;
    const int ks = blockIdx.x, qt = blockIdx.y, b = blockIdx.z;
    const int kbase = ks * (MM / KSPLIT);

    // Q tile (bf16) to smem
    {
        const __nv_bfloat16* QB = g_Qbf + ((size_t)(b * 1024 + qt * 128)) * 64;
        for (int i = tid; i < 1024; i += 256) {
            int row = i >> 3, j = i & 7;
            *(float4*)(smem + SM_QB + row * 144 + j * 16) = *(const float4*)(QB + row * 64 + j * 8);
        }
    }
    // first K chunk
    {
        const __nv_bfloat16* KH = g_Kbf + (((size_t)b << 16) + kbase) * 64;
        int i = tid, row = i >> 3, j = i & 7;
        cpa16(smem + SM_K0 + row * 144 + j * 16, KH + row * 64 + j * 8);
        i = tid + 256; row = i >> 3; j = i & 7;
        cpa16(smem + SM_K0 + row * 144 + j * 16, KH + row * 64 + j * 8);
    }
    CPA_COMMIT();
    __syncthreads();

    // Q fragments
    uint32_t qh[4][4];
    {
        const int g = 16 * warp + q4;
        const char* QHs = smem + SM_QB;
#pragma unroll
        for (int kk = 0; kk < 4; kk++) {
            int c0 = kk * 16 + t * 2;
            qh[kk][0] = *(const uint32_t*)(QHs + g * 144 + c0 * 2);
            qh[kk][1] = *(const uint32_t*)(QHs + (g + 8) * 144 + c0 * 2);
            qh[kk][2] = *(const uint32_t*)(QHs + g * 144 + (c0 + 8) * 2);
            qh[kk][3] = *(const uint32_t*)(QHs + (g + 8) * 144 + (c0 + 8) * 2);
        }
    }

    const int r0 = 16 * warp + q4;
    const int grow0 = b * 1024 + qt * 128 + r0;
    const int grow1 = grow0 + 8;
    float m_lo = -CUDART_INF_F, m_hi = -CUDART_INF_F;

    for (int i = 0; i < NCHUNK; i++) {
        char* cur = smem + SM_K0 + (i & 1) * KBUF;
        if (i + 1 < NCHUNK) {
            char* nxt = smem + SM_K0 + ((i + 1) & 1) * KBUF;
            const __nv_bfloat16* KH = g_Kbf + (((size_t)b << 16) + kbase + (i + 1) * TK) * 64;
            int u = tid, row = u >> 3, j = u & 7;
            cpa16(nxt + row * 144 + j * 16, KH + row * 64 + j * 8);
            u = tid + 256; row = u >> 3; j = u & 7;
            cpa16(nxt + row * 144 + j * 16, KH + row * 64 + j * 8);
            CPA_COMMIT();
            CPA_WAIT(1);
        } else {
            CPA_WAIT(0);
        }
        __syncthreads();

        // S = Q K^T, single bf16 pass
        float4 s[8];
        const int rb = q4 * 144 + t * 4;
#pragma unroll
        for (int nt = 0; nt < 8; nt++) {
            s[nt] = make_float4(0.f, 0.f, 0.f, 0.f);
            const char* kh = cur + nt * 8 * 144 + rb;
#pragma unroll
            for (int kk = 0; kk < 4; kk++) {
                uint32_t b0 = *(const uint32_t*)(kh + kk * 32);
                uint32_t b1 = *(const uint32_t*)(kh + kk * 32 + 16);
                mma_bf16(s[nt], qh[kk], b0, b1);
            }
        }

        // per-thread maxes (kept), quad-reduced row maxes, running update
        float mxt_lo = -CUDART_INF_F, mxt_hi = -CUDART_INF_F;
#pragma unroll
        for (int nt = 0; nt < 8; nt++) {
            mxt_lo = fmaxf(mxt_lo, fmaxf(s[nt].x, s[nt].y));
            mxt_hi = fmaxf(mxt_hi, fmaxf(s[nt].z, s[nt].w));
        }
        float mx_lo = mxt_lo, mx_hi = mxt_hi;
        mx_lo = fmaxf(mx_lo, __shfl_xor_sync(0xffffffffu, mx_lo, 1));
        mx_lo = fmaxf(mx_lo, __shfl_xor_sync(0xffffffffu, mx_lo, 2));
        mx_hi = fmaxf(mx_hi, __shfl_xor_sync(0xffffffffu, mx_hi, 1));
        mx_hi = fmaxf(mx_hi, __shfl_xor_sync(0xffffffffu, mx_hi, 2));
        m_lo = fmaxf(m_lo, mx_lo);
        m_hi = fmaxf(m_hi, mx_hi);
        const float thr0 = m_lo - MARGIN, thr1 = m_hi - MARGIN;
        const int kb = kbase + i * TK + 2 * t;

        // rare-path emission: thread enters only if it actually has a hit
        if (mxt_lo > thr0) {
            uint32_t msk = 0;
#pragma unroll
            for (int nt = 0; nt < 8; nt++) {
                msk |= (s[nt].x > thr0 ? 1u : 0u) << (2 * nt);
                msk |= (s[nt].y > thr0 ? 2u : 0u) << (2 * nt);
            }
            while (msk) {
                int bit = __ffs(msk) - 1; msk &= msk - 1;
                int key = kb + (bit >> 1) * 8 + (bit & 1);
                int pos = atomicAdd(&g_cnt[grow0], 1);
                if (pos < CAP) g_cand[(size_t)grow0 * CAP + pos] = (unsigned short)key;
            }
        }
        if (mxt_hi > thr1) {
            uint32_t msk = 0;
#pragma unroll
            for (int nt = 0; nt < 8; nt++) {
                msk |= (s[nt].z > thr1 ? 1u : 0u) << (2 * nt);
                msk |= (s[nt].w > thr1 ? 2u : 0u) << (2 * nt);
            }
            while (msk) {
                int bit = __ffs(msk) - 1; msk &= msk - 1;
                int key = kb + (bit >> 1) * 8 + (bit & 1);
                int pos = atomicAdd(&g_cnt[grow1], 1);
                if (pos < CAP) g_cand[(size_t)grow1 * CAP + pos] = (unsigned short)key;
            }
        }
        __syncthreads();
    }
}

// ------------------------------------------------------------------ stage C: exact dots + prune + softmax + epilogue
__global__ __launch_bounds__(128) void finalize_kernel(const float* __restrict__ tgt_desc,
                                                       const float* __restrict__ tgt_coords,
                                                       const float* __restrict__ tgt_w,
                                                       float* __restrict__ out) {
    __shared__ float qsh[64];
    __shared__ unsigned short ckey[CAP];
    __shared__ float cval[CAP];
    __shared__ unsigned short skey[NSCAP];
    __shared__ float sval[NSCAP];
    __shared__ float redA[4], redB[4];
    __shared__ int s_ns;
    __shared__ float vals[68];
    __shared__ float stats[2];

    const int row = blockIdx.x;           // 0..4095
    const int tid = threadIdx.x;
    const int lane = tid & 31, wp = tid >> 5;
    const int b = row >> 10, n = row & 1023;
    const int nc = min(g_cnt[row], CAP);

    if (tid < 64) qsh[tid] = g_Qf[(size_t)row * 64 + tid];
    if (tid == 0) s_ns = 0;
    for (int c = tid; c < nc; c += 128) ckey[c] = g_cand[(size_t)row * CAP + c];
    __syncthreads();

    // exact fp32 dots over all candidates
    const float4* q4p = (const float4*)qsh;
    float mx = -CUDART_INF_F;
    for (int c = tid; c < nc; c += 128) {
        const float4* kr = (const float4*)(g_Kf + ((((size_t)b << 16) + ckey[c])) * 64);
        float acc = 0.f;
#pragma unroll
        for (int j = 0; j < 16; j++) {
            float4 kv = kr[j], qv = q4p[j];
            acc += kv.x * qv.x + kv.y * qv.y + kv.z * qv.z + kv.w * qv.w;
        }
        cval[c] = acc;
        mx = fmaxf(mx, acc);
    }
#pragma unroll
    for (int o = 16; o; o >>= 1) mx = fmaxf(mx, __shfl_xor_sync(0xffffffffu, mx, o));
    if (lane == 0) redA[wp] = mx;
    __syncthreads();
    mx = fmaxf(fmaxf(redA[0], redA[1]), fmaxf(redA[2], redA[3]));

    // prune on exact scores, compact survivors with p-values
    const float thr = mx - PRUNE;
    for (int c = tid; c < nc; c += 128) {
        float v = cval[c];
        if (v > thr) {
            int pos = atomicAdd(&s_ns, 1);
            if (pos < NSCAP) {
                skey[pos] = ckey[c];
                sval[pos] = __expf(SCALE * (v - mx));
            }
        }
    }
    __syncthreads();
    const int ns = min(s_ns, NSCAP);

    // L over survivors
    float Lp = 0.f;
    for (int c = tid; c < ns; c += 128) Lp += sval[c];
#pragma unroll
    for (int o = 16; o; o >>= 1) Lp += __shfl_xor_sync(0xffffffffu, Lp, o);
    if (lane == 0) redB[wp] = Lp;
    __syncthreads();
    const float invL = 1.f / (redB[0] + redB[1] + redB[2] + redB[3]);

    // weighted channel sums over survivors only
    if (tid < 68) {
        const float* base;
        if (tid < 64)      base = tgt_desc + (((size_t)(b * 64 + tid)) << 16);
        else if (tid < 67) base = tgt_coords + (((size_t)(b * 3 + tid - 64)) << 16);
        else               base = tgt_w + (((size_t)b) << 16);
        float acc = 0.f;
        for (int c = 0; c < ns; c++) acc += sval[c] * base[skey[c]];
        vals[tid] = acc * invL;
    }
    __syncthreads();

    if (tid == 0) {
        float sum = 0.f;
#pragma unroll
        for (int c = 0; c < 64; c++) sum += vals[c];
        float mean = sum * (1.f / 64.f), var = 0.f;
#pragma unroll
        for (int c = 0; c < 64; c++) { float d = vals[c] - mean; var += d * d; }
        stats[0] = mean;
        stats[1] = rsqrtf(var * (1.f / 63.f));
    }
    __syncthreads();

    if (tid < 64)
        out[16384 + (b * 64 + tid) * 1024 + n] = (vals[tid] - stats[0]) * stats[1];

    if (tid == 64) {
        float x = vals[64], y = vals[65], z = vals[66], wgt = vals[67];
        out[(b * 3 + 0) * 1024 + n] = x;
        out[(b * 3 + 1) * 1024 + n] = y;
        out[(b * 3 + 2) * 1024 + n] = z;
        out[12288 + b * 1024 + n] = wgt;
        float rr = sqrtf(x * x + y * y + z * z);
        float az = atan2f(y, x);
        float el = asinf(z / (rr + 1e-12f));
        float u = 0.5f * (1.0f - az * (1.0f / CUDART_PI_F)) * 1024.0f;
        float v = (1.0f - (el + 0.4363323129985824f) * (1.0f / 0.4886921905584123f)) * 64.0f;
        u = fminf(fmaxf(u, 0.f), 1023.f);
        v = fminf(fmaxf(v, 0.f), 63.f);
        out[278528 + row * 2 + 0] = u;
        out[278528 + row * 2 + 1] = v;
        out[286720 + b * 1024 + n] = 1.0f;
    }
}

// ------------------------------------------------------------------
extern "C" void kernel_launch(void* const* d_in, const int* in_sizes, int n_in,
                              void* d_out, int out_size) {
    const float* tgt_coords = (const float*)d_in[1];
    const float* tgt_w      = (const float*)d_in[2];
    const float* src_desc   = (const float*)d_in[3];
    const float* tgt_desc   = (const float*)d_in[4];
    float* out = (float*)d_out;

    cudaFuncSetAttribute(select_kernel, cudaFuncAttributeMaxDynamicSharedMemorySize, SM_TOTAL);

    norm_src_kernel<<<16, 256>>>(src_desc);
    norm_tgt_kernel<<<1024, 256>>>(tgt_desc);
    zero_cnt_kernel<<<16, 256>>>();
    select_kernel<<<dim3(KSPLIT, 8, BB), 256, SM_TOTAL>>>();
    finalize_kernel<<<BB * NN, 128>>>(tgt_desc, tgt_coords, tgt_w, out);
}

// round 15
// speedup vs baseline: 5.3020x; 1.3016x over previous
#include <cuda_runtime.h>
#include <cuda_bf16.h>
#include <math_constants.h>
#include <cstdint>

#define BB 4
#define NN 1024
#define MM 65536
#define SCALE 1.5625f                 // 1/(64*0.01)
#define KSPLIT 8
#define TK 64
#define NCHUNK (MM/KSPLIT/TK)         // 128 chunks per CTA
#define MARGIN 7.5f                   // select margin (raw units)
#define PRUNE  7.0f                   // finalize prune margin (raw, exact dots)
#define CAP 2048
#define NSCAP 512

// ------------------------------------------------------------------ scratch
__device__ __nv_bfloat16 g_Qbf[BB*NN*64];          // [row][64]
__device__ float         g_Qf [BB*NN*64];          // [row][64]
__device__ __nv_bfloat16 g_Kbf[(size_t)BB*MM*64];  // [(b<<16)+m][64]
__device__ float         g_Kf [(size_t)BB*MM*64];  // [(b<<16)+m][64]
__device__ int           g_cnt[BB*NN];
__device__ int           g_rowmax[BB*NN];          // float-as-int (maxes are >0)
__device__ unsigned short g_cand[(size_t)BB*NN*CAP];

// ------------------------------------------------------------------ helpers
__device__ __forceinline__ uint32_t smem_u32(const void* p) {
    uint32_t a;
    asm("{ .reg .u64 t; cvta.to.shared.u64 t, %1; cvt.u32.u64 %0, t; }" : "=r"(a) : "l"(p));
    return a;
}
__device__ __forceinline__ void cpa16(void* dst, const void* src) {
    uint32_t d = smem_u32(dst);
    asm volatile("cp.async.cg.shared.global [%0], [%1], 16;" :: "r"(d), "l"(src) : "memory");
}
#define CPA_COMMIT() asm volatile("cp.async.commit_group;" ::: "memory")
#define CPA_WAIT(n)  asm volatile("cp.async.wait_group %0;" :: "n"(n) : "memory")

__device__ __forceinline__ void mma_bf16(float4& d, const uint32_t* a, uint32_t b0, uint32_t b1) {
    asm volatile("mma.sync.aligned.m16n8k16.row.col.f32.bf16.bf16.f32 "
                 "{%0,%1,%2,%3},{%4,%5,%6,%7},{%8,%9},{%0,%1,%2,%3};"
                 : "+f"(d.x), "+f"(d.y), "+f"(d.z), "+f"(d.w)
                 : "r"(a[0]), "r"(a[1]), "r"(a[2]), "r"(a[3]), "r"(b0), "r"(b1));
}
__device__ __forceinline__ void ldsm4(uint32_t& r0, uint32_t& r1, uint32_t& r2, uint32_t& r3,
                                      uint32_t addr) {
    asm volatile("ldmatrix.sync.aligned.m8n8.x4.shared.b16 {%0,%1,%2,%3}, [%4];"
                 : "=r"(r0), "=r"(r1), "=r"(r2), "=r"(r3) : "r"(addr));
}

// ------------------------------------------------------------------ preproc
__global__ void norm_src_kernel(const float* __restrict__ src_desc) {
    int gid = blockIdx.x * blockDim.x + threadIdx.x;   // 4096 rows
    int b = gid >> 10, n = gid & 1023;
    const float* p = src_desc + (size_t)b * 64 * NN + n;
    float xs[64]; float sum = 0.f;
#pragma unroll
    for (int c = 0; c < 64; c++) { xs[c] = p[c * NN]; sum += xs[c]; }
    float mean = sum * (1.f / 64.f), var = 0.f;
#pragma unroll
    for (int c = 0; c < 64; c++) { float d = xs[c] - mean; var += d * d; }
    float inv = rsqrtf(var * (1.f / 63.f));
#pragma unroll
    for (int c = 0; c < 64; c++) {
        float q = (xs[c] - mean) * inv;
        g_Qf[(size_t)gid * 64 + c]  = q;
        g_Qbf[(size_t)gid * 64 + c] = __float2bfloat16(q);
    }
}

__global__ void norm_tgt_kernel(const float* __restrict__ tgt_desc) {
    __shared__ uint32_t stg[8][32][33];
    int w = threadIdx.x >> 5, lane = threadIdx.x & 31;
    int gbase = blockIdx.x * 256 + w * 32;
    int gid = gbase + lane;                            // 0..262143
    int b = gid >> 16;
    int m = gid & 65535;
    const float* p = tgt_desc + (size_t)b * 64 * MM + m;
    float xs[64]; float sum = 0.f;
#pragma unroll
    for (int c = 0; c < 64; c++) { xs[c] = p[(size_t)c * MM]; sum += xs[c]; }
    float mean = sum * (1.f / 64.f), var = 0.f;
#pragma unroll
    for (int c = 0; c < 64; c++) { float d = xs[c] - mean; var += d * d; }
    float inv = rsqrtf(var * (1.f / 63.f));
    float kv[64];
#pragma unroll
    for (int c = 0; c < 64; c++) kv[c] = (xs[c] - mean) * inv;

    // bf16 transpose (rows of 64 bf16, coalesced 128B)
#pragma unroll
    for (int j = 0; j < 32; j++) {
        __nv_bfloat162 t; t.x = __float2bfloat16(kv[2 * j]); t.y = __float2bfloat16(kv[2 * j + 1]);
        stg[w][lane][j] = *(uint32_t*)&t;
    }
    __syncwarp();
    {
        uint32_t* dst = (uint32_t*)g_Kbf + (size_t)gbase * 32;
#pragma unroll
        for (int r = 0; r < 32; r++) dst[(size_t)r * 32 + lane] = stg[w][r][lane];
    }
    // fp32 transpose in two halves (rows of 64 f32)
#pragma unroll
    for (int h = 0; h < 2; h++) {
        __syncwarp();
#pragma unroll
        for (int j = 0; j < 32; j++) stg[w][lane][j] = __float_as_uint(kv[h * 32 + j]);
        __syncwarp();
        float* dst = g_Kf + (size_t)gbase * 64;
#pragma unroll
        for (int r = 0; r < 32; r++)
            dst[(size_t)r * 64 + h * 32 + lane] = __uint_as_float(stg[w][r][lane]);
    }
}

__global__ void zero_cnt_kernel() {
    int i = blockIdx.x * blockDim.x + threadIdx.x;
    if (i < BB * NN) { g_cnt[i] = 0; g_rowmax[i] = 0; }   // 0 == float 0.0 (safe lower bound)
}

// ------------------------------------------------------------------ stage B: select candidates
#define SM_QB 0
#define SM_K0 (128*144)                 // two K buffers of 64 rows x 144B
#define KBUF  (64*144)
#define SM_TOTAL (SM_K0 + 2*KBUF)       // 36864 B

__global__ __launch_bounds__(256, 2) void select_kernel() {
    extern __shared__ char smem[];
    const uint32_t smb = smem_u32(smem);
    const int tid = threadIdx.x;
    const int warp = tid >> 5, lane = tid & 31;
    const int q4 = lane >> 2, t = lane & 3;
    const int ks = blockIdx.x, qt = blockIdx.y, b = blockIdx.z;
    const int kbase = ks * (MM / KSPLIT);

    // Q tile (bf16) to smem
    {
        const __nv_bfloat16* QB = g_Qbf + ((size_t)(b * 1024 + qt * 128)) * 64;
        for (int i = tid; i < 1024; i += 256) {
            int row = i >> 3, j = i & 7;
            *(float4*)(smem + SM_QB + row * 144 + j * 16) = *(const float4*)(QB + row * 64 + j * 8);
        }
    }
    // first K chunk
    {
        const __nv_bfloat16* KH = g_Kbf + (((size_t)b << 16) + kbase) * 64;
        int i = tid, row = i >> 3, j = i & 7;
        cpa16(smem + SM_K0 + row * 144 + j * 16, KH + row * 64 + j * 8);
        i = tid + 256; row = i >> 3; j = i & 7;
        cpa16(smem + SM_K0 + row * 144 + j * 16, KH + row * 64 + j * 8);
    }
    CPA_COMMIT();
    __syncthreads();

    // Q fragments
    uint32_t qh[4][4];
    {
        const int g = 16 * warp + q4;
        const char* QHs = smem + SM_QB;
#pragma unroll
        for (int kk = 0; kk < 4; kk++) {
            int c0 = kk * 16 + t * 2;
            qh[kk][0] = *(const uint32_t*)(QHs + g * 144 + c0 * 2);
            qh[kk][1] = *(const uint32_t*)(QHs + (g + 8) * 144 + c0 * 2);
            qh[kk][2] = *(const uint32_t*)(QHs + g * 144 + (c0 + 8) * 2);
            qh[kk][3] = *(const uint32_t*)(QHs + (g + 8) * 144 + (c0 + 8) * 2);
        }
    }

    // ldmatrix per-lane row offset: lanes 0-7 -> m0 (k0..7), 8-15 -> m1 (k8..15),
    // 16-23 -> m2 (k16..23), 24-31 -> m3 (k24..31); row n = lane&7.
    const uint32_t loff = (uint32_t)((lane & 7) * 144 + (lane >> 3) * 16);

    const int r0 = 16 * warp + q4;
    const int grow0 = b * 1024 + qt * 128 + r0;
    const int grow1 = grow0 + 8;
    float m_lo = -CUDART_INF_F, m_hi = -CUDART_INF_F;
    int pend_lo = 0, pend_hi = 0;    // previous chunk's atomicMax return (float bits)

    for (int i = 0; i < NCHUNK; i++) {
        const uint32_t curb = smb + SM_K0 + (i & 1) * KBUF;
        if (i + 1 < NCHUNK) {
            char* nxt = smem + SM_K0 + ((i + 1) & 1) * KBUF;
            const __nv_bfloat16* KH = g_Kbf + (((size_t)b << 16) + kbase + (i + 1) * TK) * 64;
            int u = tid, row = u >> 3, j = u & 7;
            cpa16(nxt + row * 144 + j * 16, KH + row * 64 + j * 8);
            u = tid + 256; row = u >> 3; j = u & 7;
            cpa16(nxt + row * 144 + j * 16, KH + row * 64 + j * 8);
            CPA_COMMIT();
            CPA_WAIT(1);
        } else {
            CPA_WAIT(0);
        }
        __syncthreads();

        // S = Q K^T, single bf16 pass; K fragments via ldmatrix.x4
        float4 s[8];
#pragma unroll
        for (int nt = 0; nt < 8; nt++) {
            s[nt] = make_float4(0.f, 0.f, 0.f, 0.f);
            uint32_t base = curb + (uint32_t)(nt * 1152) + loff;
            uint32_t b0, b1, b2, b3;
            ldsm4(b0, b1, b2, b3, base);           // kk0 (b0,b1), kk1 (b2,b3)
            mma_bf16(s[nt], qh[0], b0, b1);
            mma_bf16(s[nt], qh[1], b2, b3);
            ldsm4(b0, b1, b2, b3, base + 64);      // kk2, kk3
            mma_bf16(s[nt], qh[2], b0, b1);
            mma_bf16(s[nt], qh[3], b2, b3);
        }

        // per-thread maxes, quad-reduced row maxes
        float mxt_lo = -CUDART_INF_F, mxt_hi = -CUDART_INF_F;
#pragma unroll
        for (int nt = 0; nt < 8; nt++) {
            mxt_lo = fmaxf(mxt_lo, fmaxf(s[nt].x, s[nt].y));
            mxt_hi = fmaxf(mxt_hi, fmaxf(s[nt].z, s[nt].w));
        }
        float mx_lo = mxt_lo, mx_hi = mxt_hi;
        mx_lo = fmaxf(mx_lo, __shfl_xor_sync(0xffffffffu, mx_lo, 1));
        mx_lo = fmaxf(mx_lo, __shfl_xor_sync(0xffffffffu, mx_lo, 2));
        mx_hi = fmaxf(mx_hi, __shfl_xor_sync(0xffffffffu, mx_hi, 1));
        mx_hi = fmaxf(mx_hi, __shfl_xor_sync(0xffffffffu, mx_hi, 2));

        // merge previous chunk's global max (one-chunk lag; monotonic-safe)
        float merged_lo = m_lo, merged_hi = m_hi;
        if (t == 0) {
            merged_lo = fmaxf(merged_lo, __int_as_float(pend_lo));
            merged_hi = fmaxf(merged_hi, __int_as_float(pend_hi));
        }
        merged_lo = __shfl_sync(0xffffffffu, merged_lo, lane & 28);
        merged_hi = __shfl_sync(0xffffffffu, merged_hi, lane & 28);
        m_lo = fmaxf(merged_lo, mx_lo);
        m_hi = fmaxf(merged_hi, mx_hi);
        if (t == 0 && i + 1 < NCHUNK) {
            pend_lo = atomicMax(&g_rowmax[grow0], __float_as_int(mx_lo));
            pend_hi = atomicMax(&g_rowmax[grow1], __float_as_int(mx_hi));
        }

        const float thr0 = m_lo - MARGIN, thr1 = m_hi - MARGIN;
        const int kb = kbase + i * TK + 2 * t;

        // rare-path emission: thread enters only if it actually has a hit
        if (mxt_lo > thr0) {
            uint32_t msk = 0;
#pragma unroll
            for (int nt = 0; nt < 8; nt++) {
                msk |= (s[nt].x > thr0 ? 1u : 0u) << (2 * nt);
                msk |= (s[nt].y > thr0 ? 2u : 0u) << (2 * nt);
            }
            while (msk) {
                int bit = __ffs(msk) - 1; msk &= msk - 1;
                int key = kb + (bit >> 1) * 8 + (bit & 1);
                int pos = atomicAdd(&g_cnt[grow0], 1);
                if (pos < CAP) g_cand[(size_t)grow0 * CAP + pos] = (unsigned short)key;
            }
        }
        if (mxt_hi > thr1) {
            uint32_t msk = 0;
#pragma unroll
            for (int nt = 0; nt < 8; nt++) {
                msk |= (s[nt].z > thr1 ? 1u : 0u) << (2 * nt);
                msk |= (s[nt].w > thr1 ? 2u : 0u) << (2 * nt);
            }
            while (msk) {
                int bit = __ffs(msk) - 1; msk &= msk - 1;
                int key = kb + (bit >> 1) * 8 + (bit & 1);
                int pos = atomicAdd(&g_cnt[grow1], 1);
                if (pos < CAP) g_cand[(size_t)grow1 * CAP + pos] = (unsigned short)key;
            }
        }
        __syncthreads();
    }
}

// ------------------------------------------------------------------ stage C: exact dots + prune + softmax + epilogue
__global__ __launch_bounds__(128) void finalize_kernel(const float* __restrict__ tgt_desc,
                                                       const float* __restrict__ tgt_coords,
                                                       const float* __restrict__ tgt_w,
                                                       float* __restrict__ out) {
    __shared__ float qsh[64];
    __shared__ unsigned short ckey[CAP];
    __shared__ float cval[CAP];
    __shared__ unsigned short skey[NSCAP];
    __shared__ float sval[NSCAP];
    __shared__ float redA[4], redB[4];
    __shared__ int s_ns;
    __shared__ float vals[68];
    __shared__ float stats[2];

    const int row = blockIdx.x;           // 0..4095
    const int tid = threadIdx.x;
    const int lane = tid & 31, wp = tid >> 5;
    const int b = row >> 10, n = row & 1023;
    const int nc = min(g_cnt[row], CAP);

    if (tid < 64) qsh[tid] = g_Qf[(size_t)row * 64 + tid];
    if (tid == 0) s_ns = 0;
    for (int c = tid; c < nc; c += 128) ckey[c] = g_cand[(size_t)row * CAP + c];
    __syncthreads();

    // exact fp32 dots over all candidates
    const float4* q4p = (const float4*)qsh;
    float mx = -CUDART_INF_F;
    for (int c = tid; c < nc; c += 128) {
        const float4* kr = (const float4*)(g_Kf + ((((size_t)b << 16) + ckey[c])) * 64);
        float acc = 0.f;
#pragma unroll
        for (int j = 0; j < 16; j++) {
            float4 kv = kr[j], qv = q4p[j];
            acc += kv.x * qv.x + kv.y * qv.y + kv.z * qv.z + kv.w * qv.w;
        }
        cval[c] = acc;
        mx = fmaxf(mx, acc);
    }
#pragma unroll
    for (int o = 16; o; o >>= 1) mx = fmaxf(mx, __shfl_xor_sync(0xffffffffu, mx, o));
    if (lane == 0) redA[wp] = mx;
    __syncthreads();
    mx = fmaxf(fmaxf(redA[0], redA[1]), fmaxf(redA[2], redA[3]));

    // prune on exact scores, compact survivors with p-values
    const float thr = mx - PRUNE;
    for (int c = tid; c < nc; c += 128) {
        float v = cval[c];
        if (v > thr) {
            int pos = atomicAdd(&s_ns, 1);
            if (pos < NSCAP) {
                skey[pos] = ckey[c];
                sval[pos] = __expf(SCALE * (v - mx));
            }
        }
    }
    __syncthreads();
    const int ns = min(s_ns, NSCAP);

    // L over survivors
    float Lp = 0.f;
    for (int c = tid; c < ns; c += 128) Lp += sval[c];
#pragma unroll
    for (int o = 16; o; o >>= 1) Lp += __shfl_xor_sync(0xffffffffu, Lp, o);
    if (lane == 0) redB[wp] = Lp;
    __syncthreads();
    const float invL = 1.f / (redB[0] + redB[1] + redB[2] + redB[3]);

    // weighted channel sums over survivors only
    if (tid < 68) {
        const float* base;
        if (tid < 64)      base = tgt_desc + (((size_t)(b * 64 + tid)) << 16);
        else if (tid < 67) base = tgt_coords + (((size_t)(b * 3 + tid - 64)) << 16);
        else               base = tgt_w + (((size_t)b) << 16);
        float acc = 0.f;
        for (int c = 0; c < ns; c++) acc += sval[c] * base[skey[c]];
        vals[tid] = acc * invL;
    }
    __syncthreads();

    if (tid == 0) {
        float sum = 0.f;
#pragma unroll
        for (int c = 0; c < 64; c++) sum += vals[c];
        float mean = sum * (1.f / 64.f), var = 0.f;
#pragma unroll
        for (int c = 0; c < 64; c++) { float d = vals[c] - mean; var += d * d; }
        stats[0] = mean;
        stats[1] = rsqrtf(var * (1.f / 63.f));
    }
    __syncthreads();

    if (tid < 64)
        out[16384 + (b * 64 + tid) * 1024 + n] = (vals[tid] - stats[0]) * stats[1];

    if (tid == 64) {
        float x = vals[64], y = vals[65], z = vals[66], wgt = vals[67];
        out[(b * 3 + 0) * 1024 + n] = x;
        out[(b * 3 + 1) * 1024 + n] = y;
        out[(b * 3 + 2) * 1024 + n] = z;
        out[12288 + b * 1024 + n] = wgt;
        float rr = sqrtf(x * x + y * y + z * z);
        float az = atan2f(y, x);
        float el = asinf(z / (rr + 1e-12f));
        float u = 0.5f * (1.0f - az * (1.0f / CUDART_PI_F)) * 1024.0f;
        float v = (1.0f - (el + 0.4363323129985824f) * (1.0f / 0.4886921905584123f)) * 64.0f;
        u = fminf(fmaxf(u, 0.f), 1023.f);
        v = fminf(fmaxf(v, 0.f), 63.f);
        out[278528 + row * 2 + 0] = u;
        out[278528 + row * 2 + 1] = v;
        out[286720 + b * 1024 + n] = 1.0f;
    }
}

// ------------------------------------------------------------------
extern "C" void kernel_launch(void* const* d_in, const int* in_sizes, int n_in,
                              void* d_out, int out_size) {
    const float* tgt_coords = (const float*)d_in[1];
    const float* tgt_w      = (const float*)d_in[2];
    const float* src_desc   = (const float*)d_in[3];
    const float* tgt_desc   = (const float*)d_in[4];
    float* out = (float*)d_out;

    cudaFuncSetAttribute(select_kernel, cudaFuncAttributeMaxDynamicSharedMemorySize, SM_TOTAL);

    norm_src_kernel<<<16, 256>>>(src_desc);
    norm_tgt_kernel<<<1024, 256>>>(tgt_desc);
    zero_cnt_kernel<<<16, 256>>>();
    select_kernel<<<dim3(KSPLIT, 8, BB), 256, SM_TOTAL>>>();
    finalize_kernel<<<BB * NN, 128>>>(tgt_desc, tgt_coords, tgt_w, out);
}